// round 16
// baseline (speedup 1.0000x reference)
#include <cuda_runtime.h>
#include <cstdint>

// GlobalAttentionModule_7438883356930
//
// Identity: softmax row-sums are 1 and v is constant along the softmaxed axis,
// so out = relu(GroupNorm_32(Wv @ feat + bv)). (Verified: rel_err ~1e-7.)
//
// R15 = R13 (best, 8.51us: grid=128 one wave, cluster-2 per (b,g), 512 thr,
// k split 8 ways, plain FFMA, push-stats + ONE cluster.sync) with the
// register cap lifted (__launch_bounds__(512,1)) so the 16 front-batched
// feat LDG.128s actually stay in flight together (R13 had regs=40 -> ptxas
// had split the batch, MLP ~8 instead of 16).

#define C_DIM    128
#define N_DIM    512
#define B_DIM    2
#define GROUPS   32
#define CPG      4
#define HALVES   2                     // cluster size
#define HALF_N   (N_DIM / HALVES)      // 256
#define NF4      (HALF_N / 4)          // 64 float4 n-positions
#define KSPLIT   8
#define KPART    (C_DIM / KSPLIT)      // 16
#define THREADS  (KSPLIT * NF4)        // 512
#define EPS      1e-5f

__device__ __forceinline__ uint32_t smem_u32(const void* p) {
    return (uint32_t)__cvta_generic_to_shared(p);
}

__global__ __launch_bounds__(THREADS, 1) __cluster_dims__(HALVES, 1, 1)
void fused_onewave(const float* __restrict__ feat,   // [B, C, N]
                   const float* __restrict__ Wv,     // [C, C]
                   const float* __restrict__ bv,     // [C]
                   const float* __restrict__ gamma,  // [C]
                   const float* __restrict__ beta,   // [C]
                   float* __restrict__ out)          // [B, C, N]
{
    const int bg   = blockIdx.x / HALVES;    // (batch, group)
    const int half = blockIdx.x % HALVES;    // cluster rank
    const int peer = half ^ 1;
    const int b    = bg / GROUPS;
    const int g    = bg % GROUPS;
    const int t    = threadIdx.x;

    __shared__ float4 wT[C_DIM];                    // 2 KB: wT[k] = {w_c0..w_c3}[k]
    __shared__ float4 scomb[KSPLIT][CPG][NF4];      // 32 KB k-slice partials
    __shared__ float  red_s[8], red_ss[8];
    __shared__ float2 slots[HALVES];                // partials indexed by source rank

    const int q = t >> 6;          // k-slice 0..7
    const int j = t & 63;          // float4 n index 0..63

    // ---- front-batch ALL 16 feat LDG.128 into registers (true MLP 16) ----
    float4 x[KPART];
    {
        const float* fb = feat + (size_t)b * C_DIM * N_DIM
                        + (size_t)(q * KPART) * N_DIM + half * HALF_N + 4 * j;
        #pragma unroll
        for (int kk = 0; kk < KPART; kk++)
            x[kk] = *reinterpret_cast<const float4*>(fb + (size_t)kk * N_DIM);
    }

    // ---- stage weights transposed (overlaps with feat loads in flight) ----
    {
        const int k  = t & 127;
        const int cc = t >> 7;     // 0..3
        reinterpret_cast<float*>(&wT[k])[cc] = Wv[(size_t)(g * CPG + cc) * C_DIM + k];
    }
    __syncthreads();

    // ---- GEMM: 4ch x 4n tile over this thread's 16 k values (plain FFMA) ----
    float4 a0 = make_float4(0.f, 0.f, 0.f, 0.f);
    float4 a1 = a0, a2 = a0, a3 = a0;
    #pragma unroll
    for (int kk = 0; kk < KPART; kk++) {
        const float4 wv = wT[q * KPART + kk];
        const float4 xv = x[kk];
        a0.x = fmaf(wv.x, xv.x, a0.x); a0.y = fmaf(wv.x, xv.y, a0.y);
        a0.z = fmaf(wv.x, xv.z, a0.z); a0.w = fmaf(wv.x, xv.w, a0.w);
        a1.x = fmaf(wv.y, xv.x, a1.x); a1.y = fmaf(wv.y, xv.y, a1.y);
        a1.z = fmaf(wv.y, xv.z, a1.z); a1.w = fmaf(wv.y, xv.w, a1.w);
        a2.x = fmaf(wv.z, xv.x, a2.x); a2.y = fmaf(wv.z, xv.y, a2.y);
        a2.z = fmaf(wv.z, xv.z, a2.z); a2.w = fmaf(wv.z, xv.w, a2.w);
        a3.x = fmaf(wv.w, xv.x, a3.x); a3.y = fmaf(wv.w, xv.y, a3.y);
        a3.z = fmaf(wv.w, xv.z, a3.z); a3.w = fmaf(wv.w, xv.w, a3.w);
    }

    // ---- publish k-slice partials ----
    scomb[q][0][j] = a0;
    scomb[q][1][j] = a1;
    scomb[q][2][j] = a2;
    scomb[q][3][j] = a3;
    __syncthreads();

    // ---- fold by 256 epilogue threads; block-level stats ----
    const int ecc = t >> 6;        // 0..3 for t<256
    const int ej  = t & 63;
    float4 v = make_float4(0.f, 0.f, 0.f, 0.f);
    float ga_raw = 0.f, be = 0.f;

    if (t < 256) {
        #pragma unroll
        for (int r = 0; r < KSPLIT; r++) {
            const float4 p = scomb[r][ecc][ej];
            v.x += p.x; v.y += p.y; v.z += p.z; v.w += p.w;
        }
        const int c  = g * CPG + ecc;
        const float bb = bv[c];
        v.x += bb; v.y += bb; v.z += bb; v.w += bb;

        ga_raw = gamma[c];         // prefetch; hides under barrier
        be     = beta[c];

        float s  = v.x + v.y + v.z + v.w;
        float ss = v.x * v.x + v.y * v.y + v.z * v.z + v.w * v.w;
        #pragma unroll
        for (int o = 16; o > 0; o >>= 1) {
            s  += __shfl_xor_sync(0xffffffffu, s,  o);
            ss += __shfl_xor_sync(0xffffffffu, ss, o);
        }
        const int warp = t >> 5, lane = t & 31;     // warps 0..7
        if (lane == 0) { red_s[warp] = s; red_ss[warp] = ss; }
    }
    __syncthreads();

    // ---- t0 PUSHES its block partial into BOTH blocks' slots[half] ----
    if (t == 0) {
        float ts = 0.f, tss = 0.f;
        #pragma unroll
        for (int i = 0; i < 8; i++) { ts += red_s[i]; tss += red_ss[i]; }

        const uint32_t lslot = smem_u32(&slots[half]);
        uint32_t rslot;
        asm("mapa.shared::cluster.u32 %0, %1, %2;"
            : "=r"(rslot) : "r"(lslot), "r"(peer));
        asm volatile("st.shared::cluster.v2.f32 [%0], {%1, %2};"
                     :: "r"(rslot), "f"(ts), "f"(tss) : "memory");
        slots[half] = make_float2(ts, tss);
    }

    // ---- SINGLE cluster barrier: arrive(release) orders t0's remote store;
    //      wait(acquire) makes both slots visible to every thread ----
    asm volatile("barrier.cluster.arrive.aligned;" ::: "memory");
    asm volatile("barrier.cluster.wait.aligned;"   ::: "memory");

    // ---- redundant per-thread stats (fixed order -> deterministic),
    //      then normalize + affine + relu + store ----
    if (t < 256) {
        const float2 p0 = slots[0];
        const float2 p1 = slots[1];
        const float inv = 1.0f / (float)(CPG * N_DIM);
        const float m   = (p0.x + p1.x) * inv;
        const float var = (p0.y + p1.y) * inv - m * m;
        const float ga  = ga_raw * rsqrtf(var + EPS);

        const int c  = g * CPG + ecc;
        const int n0 = half * HALF_N + 4 * ej;

        float4 o4;
        o4.x = fmaxf(fmaf(v.x - m, ga, be), 0.f);
        o4.y = fmaxf(fmaf(v.y - m, ga, be), 0.f);
        o4.z = fmaxf(fmaf(v.z - m, ga, be), 0.f);
        o4.w = fmaxf(fmaf(v.w - m, ga, be), 0.f);
        *reinterpret_cast<float4*>(out + ((size_t)b * C_DIM + c) * N_DIM + n0) = o4;
    }
    // Exit safe: all remote stores happened before the cluster barrier; after
    // it, no thread touches peer SMEM.
}

extern "C" void kernel_launch(void* const* d_in, const int* in_sizes, int n_in,
                              void* d_out, int out_size)
{
    // 0 feat, 1 Wk, 2 bk, 3 Wq, 4 bq, 5 Wv, 6 bv, 7 gn_v_g, 8 gn_v_b, ...
    const float* feat = (const float*)d_in[0];
    const float* Wv   = (const float*)d_in[5];
    const float* bv   = (const float*)d_in[6];
    const float* gn_g = (const float*)d_in[7];
    const float* gn_b = (const float*)d_in[8];
    float* out = (float*)d_out;

    fused_onewave<<<B_DIM * GROUPS * HALVES, THREADS>>>(feat, Wv, bv, gn_g, gn_b, out);
}